// round 9
// baseline (speedup 1.0000x reference)
#include <cuda_runtime.h>
#include <math.h>

#define NPTS   8192
#define NB     4
#define NPOINT 409
#define NQ     (NB*NPOINT)   // 1636
#define UNIBLK ((NQ + 7)/8)  // 205
#define FPS_CL 4             // FPS cluster size (CTAs per batch)
#define FPS_BLKS (NB*FPS_CL) // 16

// ---------------- device scratch (no allocations allowed) ----------------
__device__ double g_rep_sum;
__device__ double g_uni_sum[5];
__device__ float  g_newxyz[NQ*3];
__device__ unsigned int g_done;

// Exact (non-FMA-contracted) squared distance, matching XLA's sub->mul->add.
__device__ __forceinline__ float sqdist3(float ax,float ay,float az,
                                         float bx,float by,float bz){
    float dx=__fsub_rn(ax,bx), dy=__fsub_rn(ay,by), dz=__fsub_rn(az,bz);
    return __fadd_rn(__fadd_rn(__fmul_rn(dx,dx),__fmul_rn(dy,dy)),__fmul_rn(dz,dz));
}

// ---- packed f32x2 helpers (per-lane rn rounding == scalar rn ops) ----
__device__ __forceinline__ unsigned long long pk2(float lo, float hi){
    unsigned long long r;
    asm("mov.b64 %0, {%1, %2};" : "=l"(r) : "f"(lo), "f"(hi));
    return r;
}
__device__ __forceinline__ void unpk2(unsigned long long v, float& lo, float& hi){
    asm("mov.b64 {%0, %1}, %2;" : "=f"(lo), "=f"(hi) : "l"(v));
}
__device__ __forceinline__ unsigned long long add2(unsigned long long a, unsigned long long b){
    unsigned long long r; asm("add.rn.f32x2 %0, %1, %2;" : "=l"(r) : "l"(a), "l"(b)); return r;
}
__device__ __forceinline__ unsigned long long mul2(unsigned long long a, unsigned long long b){
    unsigned long long r; asm("mul.rn.f32x2 %0, %1, %2;" : "=l"(r) : "l"(a), "l"(b)); return r;
}

// ---- cluster / mbarrier helpers ----
__device__ __forceinline__ unsigned int s2u(const void* p){
    unsigned int a;
    asm("{ .reg .u64 t; cvta.to.shared.u64 t, %1; cvt.u32.u64 %0, t; }" : "=r"(a) : "l"(p));
    return a;
}
__device__ __forceinline__ unsigned int ctarank(){
    unsigned int r; asm("mov.u32 %0, %%cluster_ctarank;" : "=r"(r)); return r;
}
__device__ __forceinline__ void mbar_init(unsigned int bar, unsigned int cnt){
    asm volatile("mbarrier.init.shared.b64 [%0], %1;" :: "r"(bar), "r"(cnt) : "memory");
}
// store one u64 slot into CTA `rank`'s smem and arrive (release.cluster) on its barrier
__device__ __forceinline__ void slot_arrive(unsigned int slot_addr, unsigned int bar_addr,
                                            unsigned long long v, unsigned int rank){
    unsigned int rs, rb;
    asm volatile("mapa.shared::cluster.u32 %0, %1, %2;" : "=r"(rs) : "r"(slot_addr), "r"(rank));
    asm volatile("mapa.shared::cluster.u32 %0, %1, %2;" : "=r"(rb) : "r"(bar_addr),  "r"(rank));
    asm volatile("st.shared::cluster.u64 [%0], %1;" :: "r"(rs), "l"(v) : "memory");
    asm volatile("mbarrier.arrive.release.cluster.shared::cluster.b64 _, [%0];" :: "r"(rb) : "memory");
}
__device__ __forceinline__ void mbar_wait_parity_cluster(unsigned int bar, unsigned int parity){
    asm volatile(
        "{\n\t"
        ".reg .pred P1;\n\t"
        "WAIT_LOOP_%=:\n\t"
        "mbarrier.try_wait.parity.acquire.cluster.shared::cta.b64 P1, [%0], %1, 0x989680;\n\t"
        "@P1 bra.uni WAIT_DONE_%=;\n\t"
        "bra.uni WAIT_LOOP_%=;\n\t"
        "WAIT_DONE_%=:\n\t"
        "}" :: "r"(bar), "r"(parity) : "memory");
}
__device__ __forceinline__ void cluster_sync_all(){
    asm volatile("barrier.cluster.arrive.aligned;" ::: "memory");
    asm volatile("barrier.cluster.wait.aligned;"   ::: "memory");
}
__device__ __forceinline__ unsigned long long u64max(unsigned long long a, unsigned long long b){
    return (a>b)? a : b;
}

__global__ void init_kernel(){
    if (threadIdx.x==0){ g_rep_sum=0.0; g_done=0u; }
    if (threadIdx.x<5)  g_uni_sum[threadIdx.x]=0.0;
}

// =====================================================================
// Fused kernel (cluster dims 4): blocks 0..15 = FPS, 4-CTA cluster per
// batch, 2048 points per CTA, DSMEM all-to-all argmax per iteration.
// Blocks 16..143 = repulsion loss (unchanged proven numerics).
// =====================================================================
#define TILE 2048

__global__ __launch_bounds__(256,1) __cluster_dims__(FPS_CL,1,1)
void fps_rep_kernel(const float* __restrict__ pcd){
    __shared__ float4 s_tile[TILE];                          // repulsion role
    __shared__ __align__(8) unsigned long long s_slot[2][32];// fps role (parity buffers)
    __shared__ __align__(8) unsigned long long s_bar;
    __shared__ float s_red[8];
    const int tid = threadIdx.x;

    if (blockIdx.x < FPS_BLKS){
        // ---------------- FPS role: 4 CTAs per batch ----------------
        const unsigned int rank = ctarank();                 // 0..3
        const int b = blockIdx.x / FPS_CL;
        const float* __restrict__ P = pcd + b*NPTS*3;
        const int pbase = (int)rank * (NPTS/FPS_CL);         // 2048-point chunk
        const int lane = tid & 31, wid = tid >> 5;
        const unsigned int slot_base = s2u(&s_slot[0][0]);
        const unsigned int bar_addr  = s2u(&s_bar);

        // 8 points/thread as 4 packed pairs; negated coords so px-x == px+(-x)
        unsigned long long nx[4], ny[4], nz[4];
        float dmin[8];
        #pragma unroll
        for (int m=0;m<4;m++){
            const int j0 = pbase + tid + (2*m)*256;
            const int j1 = j0 + 256;
            nx[m] = pk2(-P[3*j0  ], -P[3*j1  ]);
            ny[m] = pk2(-P[3*j0+1], -P[3*j1+1]);
            nz[m] = pk2(-P[3*j0+2], -P[3*j1+2]);
            dmin[2*m] = 1e10f; dmin[2*m+1] = 1e10f;
        }
        if (tid==0) mbar_init(bar_addr, 32);                 // 4 CTAs x 8 warp leaders
        __syncthreads();
        cluster_sync_all();                                  // barriers visible cluster-wide

        float px=P[0], py=P[1], pz=P[2];
        for (int t=0;t<NPOINT;t++){
            if (rank==0 && tid==0){
                const int qi = b*NPOINT + t;
                g_newxyz[3*qi]=px; g_newxyz[3*qi+1]=py; g_newxyz[3*qi+2]=pz;
            }
            const unsigned long long px2=pk2(px,px), py2=pk2(py,py), pz2=pk2(pz,pz);
            float bv0=-1.f, bv1=-1.f; int bj0=0, bj1=0;
            #pragma unroll
            for (int m=0;m<4;m++){
                const unsigned long long dx=add2(px2,nx[m]);
                const unsigned long long dy=add2(py2,ny[m]);
                const unsigned long long dz=add2(pz2,nz[m]);
                const unsigned long long s2=add2(add2(mul2(dx,dx),mul2(dy,dy)),mul2(dz,dz));
                float d0,d1; unpk2(s2,d0,d1);
                const float n0=fminf(dmin[2*m  ],d0); dmin[2*m  ]=n0;
                const float n1=fminf(dmin[2*m+1],d1); dmin[2*m+1]=n1;
                if (n0>bv0){ bv0=n0; bj0=pbase+tid+(2*m  )*256; }  // strict > keeps lowest j per chain
                if (n1>bv1){ bv1=n1; bj1=pbase+tid+(2*m+1)*256; }
            }
            // merge chains: max value, ties -> smaller index
            float bv = bv0; int bj = bj0;
            if (bv1>bv0 || (bv1==bv0 && bj1<bj0)){ bv=bv1; bj=bj1; }

            // warp argmax via redux (dmin>=0 so uint order == float order)
            const unsigned vb = __float_as_uint(bv);
            const unsigned mx = __reduce_max_sync(0xffffffffu, vb);
            const unsigned cand = (vb==mx)? (unsigned)bj : 0xffffffffu;
            const unsigned mnj = __reduce_min_sync(0xffffffffu, cand);

            const int par = t & 1;
            if (lane==0){
                // pack value|inverted-index: u64 max == (max val, min idx) like jnp.argmax
                const unsigned long long pk =
                    (((unsigned long long)mx)<<32) | (unsigned int)(NPTS-1-(int)mnj);
                const unsigned int my_slot = slot_base + (unsigned)((par*32 + rank*8 + wid)*8);
                #pragma unroll
                for (unsigned int r=0;r<FPS_CL;r++)
                    slot_arrive(my_slot, bar_addr, pk, r);
            }
            mbar_wait_parity_cluster(bar_addr, (unsigned)par);

            // redundant 32-slot max in every thread (broadcast LDS)
            unsigned long long m0 = s_slot[par][0];
            #pragma unroll
            for (int k=1;k<32;k++) m0 = u64max(m0, s_slot[par][k]);
            const int j = (NPTS-1) - (int)(m0 & 0xffffffffull);
            px=P[3*j]; py=P[3*j+1]; pz=P[3*j+2];   // uniform-address broadcast load
        }
        cluster_sync_all();                        // no early exit while peers may write
    } else {
        // ---------------- repulsion role (unchanged, proven numerics) ----------------
        const int rb = blockIdx.x - FPS_BLKS;  // 0..127, 32 blocks per batch
        const int b  = rb >> 5;
        const int i  = ((rb & 31) << 8) + tid; // point index 0..8191
        const float* __restrict__ P = pcd + b*NPTS*3;
        const float qx=P[3*i], qy=P[3*i+1], qz=P[3*i+2];
        const float R2 = (float)(0.07*0.07);
        float best[5] = {3.4e38f,3.4e38f,3.4e38f,3.4e38f,3.4e38f};
        float h0 = 0.f; int cnt = 0;

        for (int base=0; base<NPTS; base+=TILE){
            for (int j=tid; j<TILE; j+=256){
                const int g = base + j;
                s_tile[j] = make_float4(P[3*g],P[3*g+1],P[3*g+2],0.f);
            }
            __syncthreads();
            for (int j=0;j<TILE;j++){
                const float4 tp = s_tile[j];
                const float dd = sqdist3(qx,qy,qz,tp.x,tp.y,tp.z);
                if (dd<=R2 && cnt<20){          // first 20 hits in ascending index order
                    if (cnt==0) h0 = dd;
                    cnt++;
                    if (dd < best[4]){
                        best[4]=dd;
                        #pragma unroll
                        for (int k=3;k>=0;k--){
                            if (best[k+1]<best[k]){ float tm=best[k]; best[k]=best[k+1]; best[k+1]=tm; }
                        }
                    }
                }
            }
            __syncthreads();
        }
        for (int t=cnt; t<20; t++){
            if (!(h0 < best[4])) break;
            best[4]=h0;
            #pragma unroll
            for (int k=3;k>=0;k--){
                if (best[k+1]<best[k]){ float tm=best[k]; best[k]=best[k+1]; best[k+1]=tm; }
            }
        }
        const float H2 = (float)(0.03*0.03);
        float s = 0.f;
        #pragma unroll
        for (int k=1;k<5;k++){
            const float d5 = fmaxf(best[k], 0.f);
            const float ds = sqrtf(d5);
            const float w  = expf((-d5)/H2);
            s = __fadd_rn(s, __fsub_rn(0.07f, __fmul_rn(ds,w)));
        }
        #pragma unroll
        for (int o=16;o;o>>=1) s += __shfl_down_sync(0xffffffffu, s, o);
        if ((tid&31)==0) s_red[tid>>5] = s;
        __syncthreads();
        if (tid==0){
            float tt=0.f;
            #pragma unroll
            for (int w=0;w<8;w++) tt += s_red[w];
            atomicAdd(&g_rep_sum, (double)tt);
        }
    }
}

// =====================================================================
// Fused uniform loss (one coalesced scan per query for all 5 radii) +
// in-kernel finalization by the last block (saves the fin launch).
// =====================================================================
#define UCAP 192          // master hit-list capacity (actual hits ~<=25)

__global__ __launch_bounds__(256) void uni_fused_kernel(const float* __restrict__ pcd,
                                                        float* __restrict__ out){
    __shared__ float4        s_pts[8][UCAP];     // {x,y,z,d^2}
    __shared__ unsigned char s_sel[8][136];
    __shared__ float         s_acc[5];
    const int tid = threadIdx.x, lane = tid & 31, w = tid >> 5;
    if (tid < 5) s_acc[tid] = 0.f;
    __syncthreads();

    const int qi = blockIdx.x * 8 + w;
    float wsum[5] = {0.f,0.f,0.f,0.f,0.f};

    const double pv[5]  = {0.004,0.008,0.01,0.012,0.016};
    const int    nss[5] = {32,65,81,98,131};
    float r2s[5], expf_[5], denf_[5];
    #pragma unroll
    for (int i=0;i<5;i++){
        double r = sqrt(pv[i]*1.0);
        r2s[i] = (float)(r*r);
        double disk = 3.14159265358979323846 * 1.0 * pv[i] / (double)nss[i];
        double el   = sqrt(2.0*disk/1.732);
        expf_[i] = (float)el;
        denf_[i] = (float)(el + 1e-8);
    }
    const float r2max = r2s[4];

    if (qi < NQ){
        const int b = qi / NPOINT;
        const float* __restrict__ P = pcd + b*NPTS*3;
        const float qx=g_newxyz[3*qi], qy=g_newxyz[3*qi+1], qz=g_newxyz[3*qi+2];

        // ---- phase 1: coalesced scan + warp-ballot compaction ----
        int cnt = 0;
        for (int base=0; base<NPTS; base+=32){
            const int j = base + lane;
            const float px=P[3*j], py=P[3*j+1], pz=P[3*j+2];
            const float dd = sqdist3(px,py,pz,qx,qy,qz);
            const bool hit = (dd <= r2max);
            const unsigned msk = __ballot_sync(0xffffffffu, hit);
            if (hit){
                const int pos = cnt + __popc(msk & ((1u<<lane)-1u));
                if (pos < UCAP) s_pts[w][pos] = make_float4(px,py,pz,dd);
            }
            cnt += __popc(msk);
        }
        if (cnt > UCAP) cnt = UCAP;
        __syncwarp();

        // ---- phase 2: per percentage ----
        #pragma unroll
        for (int i=0;i<5;i++){
            const int   ns  = nss[i];
            const float r2  = r2s[i];
            int K = 0;
            for (int base=0; base<cnt && K<ns; base+=32){
                const int m = base + lane;
                const bool sel = (m < cnt) && (s_pts[w][m].w <= r2);
                const unsigned msk = __ballot_sync(0xffffffffu, sel);
                if (sel){
                    const int pos = K + __popc(msk & ((1u<<lane)-1u));
                    if (pos < ns) s_sel[w][pos] = (unsigned char)m;
                }
                K += __popc(msk);
            }
            if (K > ns) K = ns;
            __syncwarp();

            const int Ppad = ns - K;
            float s = 0.f;
            const float4 p0 = s_pts[w][s_sel[w][0]];
            for (int r = lane; r < K; r += 32){
                const float4 a = s_pts[w][s_sel[w][r]];
                float m1 = 3.4e38f, m2 = 3.4e38f;
                for (int bb=0; bb<K; bb++){
                    const float4 pb = s_pts[w][s_sel[w][bb]];
                    const float dd = sqdist3(a.x,a.y,a.z,pb.x,pb.y,pb.z);
                    if (dd < m1){ m2 = m1; m1 = dd; }
                    else if (dd < m2){ m2 = dd; }
                }
                if (Ppad > 0){
                    const float dd = sqdist3(a.x,a.y,a.z,p0.x,p0.y,p0.z);
                    if (dd < m1){ m2 = m1; m1 = dd; } else if (dd < m2){ m2 = dd; }
                    if (Ppad > 1){
                        if (dd < m1){ m2 = m1; m1 = dd; } else if (dd < m2){ m2 = dd; }
                    }
                }
                const float rud = sqrtf(fabsf(__fadd_rn(m2, 1e-8f)));
                const float dv  = __fsub_rn(rud, expf_[i]);
                s = __fadd_rn(s, __fmul_rn(dv,dv)/denf_[i]);
            }
            if (lane == 0 && Ppad > 0){
                const float rud = sqrtf(fabsf(__fadd_rn(0.f, 1e-8f)));
                const float dv  = __fsub_rn(rud, expf_[i]);
                s = __fadd_rn(s, (float)Ppad * (__fmul_rn(dv,dv)/denf_[i]));
            }
            #pragma unroll
            for (int o=16;o;o>>=1) s += __shfl_down_sync(0xffffffffu, s, o);
            wsum[i] = s;
            __syncwarp();
        }
        if (lane == 0){
            #pragma unroll
            for (int i=0;i<5;i++) atomicAdd(&s_acc[i], wsum[i]);
        }
    }
    __syncthreads();
    if (tid < 5) atomicAdd(&g_uni_sum[tid], (double)s_acc[tid]);
    __syncthreads();

    // ---- finalization by the last block to finish ----
    if (tid == 0){
        __threadfence();
        const unsigned v = atomicAdd(&g_done, 1u);
        if (v == (unsigned)(UNIBLK - 1)){
            const double pvf[5]  = {0.004,0.008,0.01,0.012,0.016};
            const int    nssf[5] = {32,65,81,98,131};
            double u = 0.0;
            for (int i=0;i<5;i++){
                const double m = g_uni_sum[i] / ((double)NQ * (double)nssf[i]);
                const double wgt = (pvf[i]*100.0)*(pvf[i]*100.0);
                u += m*wgt;
            }
            u /= 5.0;
            out[0] = (float)u;
            out[1] = (float)(g_rep_sum / 131072.0);   // mean over B*N*4
        }
    }
}

extern "C" void kernel_launch(void* const* d_in, const int* in_sizes, int n_in,
                              void* d_out, int out_size){
    (void)in_sizes; (void)n_in; (void)out_size;
    const float* pcd = (const float*)d_in[0];
    float* out = (float*)d_out;

    init_kernel<<<1,32>>>();
    fps_rep_kernel<<<FPS_BLKS + NB*32, 256>>>(pcd);  // 16 FPS (4 clusters of 4) + 128 repulsion
    uni_fused_kernel<<<UNIBLK, 256>>>(pcd, out);     // 205 blocks; last one finalizes
}

// round 10
// speedup vs baseline: 2.3456x; 2.3456x over previous
#include <cuda_runtime.h>
#include <math.h>

#define NPTS   8192
#define NB     4
#define NPOINT 409
#define NQ     (NB*NPOINT)   // 1636
#define UNIBLK ((NQ + 7)/8)  // 205
#define FPS_CL 4             // FPS cluster size (CTAs per batch)
#define FPS_BLKS (NB*FPS_CL) // 16

// ---------------- device scratch (no allocations allowed) ----------------
__device__ double g_rep_sum;
__device__ double g_uni_sum[5];
__device__ float  g_newxyz[NQ*3];
__device__ unsigned int g_done;

// Exact (non-FMA-contracted) squared distance, matching XLA's sub->mul->add.
__device__ __forceinline__ float sqdist3(float ax,float ay,float az,
                                         float bx,float by,float bz){
    float dx=__fsub_rn(ax,bx), dy=__fsub_rn(ay,by), dz=__fsub_rn(az,bz);
    return __fadd_rn(__fadd_rn(__fmul_rn(dx,dx),__fmul_rn(dy,dy)),__fmul_rn(dz,dz));
}

// ---- cluster helpers ----
__device__ __forceinline__ unsigned int s2u(const void* p){
    unsigned int a;
    asm("{ .reg .u64 t; cvta.to.shared.u64 t, %1; cvt.u32.u64 %0, t; }" : "=r"(a) : "l"(p));
    return a;
}
__device__ __forceinline__ unsigned int ctarank(){
    unsigned int r; asm("mov.u32 %0, %%cluster_ctarank;" : "=r"(r)); return r;
}
// plain DSMEM store of one u64 into CTA `rank`'s smem (tag embedded in word; no fence)
__device__ __forceinline__ void slot_store(unsigned int slot_addr, unsigned long long v,
                                           unsigned int rank){
    unsigned int rs;
    asm volatile("mapa.shared::cluster.u32 %0, %1, %2;" : "=r"(rs) : "r"(slot_addr), "r"(rank));
    asm volatile("st.shared::cluster.u64 [%0], %1;" :: "r"(rs), "l"(v) : "memory");
}
__device__ __forceinline__ unsigned long long ld_slot_vol(unsigned int addr){
    unsigned long long v;
    asm volatile("ld.volatile.shared.u64 %0, [%1];" : "=l"(v) : "r"(addr));
    return v;
}
__device__ __forceinline__ void cluster_sync_all(){
    asm volatile("barrier.cluster.arrive.aligned;" ::: "memory");
    asm volatile("barrier.cluster.wait.aligned;"   ::: "memory");
}
__device__ __forceinline__ unsigned long long u64max(unsigned long long a, unsigned long long b){
    return (a>b)? a : b;
}

__global__ void init_kernel(){
    if (threadIdx.x==0){ g_rep_sum=0.0; g_done=0u; }
    if (threadIdx.x<5)  g_uni_sum[threadIdx.x]=0.0;
}

// =====================================================================
// Fused kernel (cluster dims 4): blocks 0..15 = FPS (4-CTA cluster per
// batch, 2048 pts/CTA, fence-free tagged-word DSMEM argmax exchange).
// Blocks 16..143 = repulsion loss (unchanged proven numerics).
// =====================================================================
#define TILE 2048

__global__ __launch_bounds__(256,1) __cluster_dims__(FPS_CL,1,1)
void fps_rep_kernel(const float* __restrict__ pcd){
    __shared__ float4 s_tile[TILE];                          // repulsion role
    __shared__ __align__(8) unsigned long long s_slot[2][FPS_CL]; // published CTA-bests (parity)
    __shared__ __align__(8) unsigned long long s_loc[8];     // local warp bests
    __shared__ float s_red[8];
    const int tid = threadIdx.x;

    if (blockIdx.x < FPS_BLKS){
        // ---------------- FPS role: 4 CTAs per batch, 8 pts/thread ----------------
        const unsigned int rank = ctarank();                 // 0..3
        const int b = blockIdx.x / FPS_CL;
        const float* __restrict__ P = pcd + b*NPTS*3;
        const int pbase = (int)rank * (NPTS/FPS_CL);         // 2048-point chunk
        const int lane = tid & 31;
        const unsigned int slot0 = s2u(&s_slot[0][0]);

        float x[8], y[8], z[8], dmin[8];
        #pragma unroll
        for (int k=0;k<8;k++){
            const int j = pbase + tid + k*256;
            x[k]=P[3*j]; y[k]=P[3*j+1]; z[k]=P[3*j+2];
            dmin[k]=1e10f;
        }
        if (tid < 2*FPS_CL)                                  // invalid tag 511 (> max t=408)
            s_slot[tid>>2][tid&3] = 0x1FFull;
        __syncthreads();
        cluster_sync_all();                                  // inits visible before any publish

        float px=P[0], py=P[1], pz=P[2];
        for (int t=0;t<NPOINT;t++){
            if (rank==0 && tid==0){
                const int qi = b*NPOINT + t;
                g_newxyz[3*qi]=px; g_newxyz[3*qi+1]=py; g_newxyz[3*qi+2]=pz;
            }
            float bv=-1.f; int bj=0;
            #pragma unroll
            for (int k=0;k<8;k++){
                const float d  = sqdist3(x[k],y[k],z[k],px,py,pz);
                const float nd = fminf(dmin[k], d);
                dmin[k] = nd;
                if (nd > bv){ bv=nd; bj=pbase+tid+k*256; }   // strict > keeps lowest j in-thread
            }
            // warp argmax via redux (dmin>=0 so uint order == float order)
            const unsigned vb = __float_as_uint(bv);
            const unsigned mx = __reduce_max_sync(0xffffffffu, vb);
            const unsigned cand = (vb==mx)? (unsigned)bj : 0xffffffffu;
            const unsigned mnj = __reduce_min_sync(0xffffffffu, cand);
            const unsigned tag = (unsigned)t & 511u;
            if (lane==0)
                s_loc[tid>>5] = (((unsigned long long)mx)<<32)
                              | (((unsigned long long)(NPTS-1-(int)mnj))<<9)
                              | (unsigned long long)tag;
            __syncthreads();
            const int par = t & 1;
            if (tid==0){
                unsigned long long m = s_loc[0];
                #pragma unroll
                for (int k=1;k<8;k++) m = u64max(m, s_loc[k]);
                const unsigned int my = slot0 + (unsigned)((par*FPS_CL + (int)rank)*8);
                #pragma unroll
                for (unsigned int r=0;r<FPS_CL;r++) slot_store(my, m, r);  // one word per CTA
            }
            // consumers: poll local slots until all 4 carry this iteration's tag
            const unsigned int pb2 = slot0 + (unsigned)(par*FPS_CL*8);
            unsigned long long v0,v1,v2,v3;
            do {
                v0=ld_slot_vol(pb2); v1=ld_slot_vol(pb2+8);
                v2=ld_slot_vol(pb2+16); v3=ld_slot_vol(pb2+24);
            } while ((((unsigned)v0 ^ tag) & 511u) | (((unsigned)v1 ^ tag) & 511u) |
                     (((unsigned)v2 ^ tag) & 511u) | (((unsigned)v3 ^ tag) & 511u));
            const unsigned long long m0 = u64max(u64max(v0,v1), u64max(v2,v3));
            const int j = (NPTS-1) - (int)((m0>>9) & 0x1FFFull);
            px=P[3*j]; py=P[3*j+1]; pz=P[3*j+2];   // uniform-address broadcast load
        }
        cluster_sync_all();                        // no early exit with stores in flight
    } else {
        // ---------------- repulsion role (unchanged, proven numerics) ----------------
        const int rb = blockIdx.x - FPS_BLKS;  // 0..127, 32 blocks per batch
        const int b  = rb >> 5;
        const int i  = ((rb & 31) << 8) + tid; // point index 0..8191
        const float* __restrict__ P = pcd + b*NPTS*3;
        const float qx=P[3*i], qy=P[3*i+1], qz=P[3*i+2];
        const float R2 = (float)(0.07*0.07);
        float best[5] = {3.4e38f,3.4e38f,3.4e38f,3.4e38f,3.4e38f};
        float h0 = 0.f; int cnt = 0;

        for (int base=0; base<NPTS; base+=TILE){
            for (int j=tid; j<TILE; j+=256){
                const int g = base + j;
                s_tile[j] = make_float4(P[3*g],P[3*g+1],P[3*g+2],0.f);
            }
            __syncthreads();
            for (int j=0;j<TILE;j++){
                const float4 tp = s_tile[j];
                const float dd = sqdist3(qx,qy,qz,tp.x,tp.y,tp.z);
                if (dd<=R2 && cnt<20){          // first 20 hits in ascending index order
                    if (cnt==0) h0 = dd;
                    cnt++;
                    if (dd < best[4]){
                        best[4]=dd;
                        #pragma unroll
                        for (int k=3;k>=0;k--){
                            if (best[k+1]<best[k]){ float tm=best[k]; best[k]=best[k+1]; best[k+1]=tm; }
                        }
                    }
                }
            }
            __syncthreads();
        }
        for (int t=cnt; t<20; t++){
            if (!(h0 < best[4])) break;
            best[4]=h0;
            #pragma unroll
            for (int k=3;k>=0;k--){
                if (best[k+1]<best[k]){ float tm=best[k]; best[k]=best[k+1]; best[k+1]=tm; }
            }
        }
        const float H2 = (float)(0.03*0.03);
        float s = 0.f;
        #pragma unroll
        for (int k=1;k<5;k++){
            const float d5 = fmaxf(best[k], 0.f);
            const float ds = sqrtf(d5);
            const float w  = expf((-d5)/H2);
            s = __fadd_rn(s, __fsub_rn(0.07f, __fmul_rn(ds,w)));
        }
        #pragma unroll
        for (int o=16;o;o>>=1) s += __shfl_down_sync(0xffffffffu, s, o);
        if ((tid&31)==0) s_red[tid>>5] = s;
        __syncthreads();
        if (tid==0){
            float tt=0.f;
            #pragma unroll
            for (int w=0;w<8;w++) tt += s_red[w];
            atomicAdd(&g_rep_sum, (double)tt);
        }
    }
}

// =====================================================================
// Fused uniform loss (one coalesced scan per query for all 5 radii) +
// in-kernel finalization by the last block.
// =====================================================================
#define UCAP 192          // master hit-list capacity (actual hits ~<=25)

__global__ __launch_bounds__(256) void uni_fused_kernel(const float* __restrict__ pcd,
                                                        float* __restrict__ out){
    __shared__ float4        s_pts[8][UCAP];     // {x,y,z,d^2}
    __shared__ unsigned char s_sel[8][136];
    __shared__ float         s_acc[5];
    const int tid = threadIdx.x, lane = tid & 31, w = tid >> 5;
    if (tid < 5) s_acc[tid] = 0.f;
    __syncthreads();

    const int qi = blockIdx.x * 8 + w;
    float wsum[5] = {0.f,0.f,0.f,0.f,0.f};

    const double pv[5]  = {0.004,0.008,0.01,0.012,0.016};
    const int    nss[5] = {32,65,81,98,131};
    float r2s[5], expf_[5], denf_[5];
    #pragma unroll
    for (int i=0;i<5;i++){
        double r = sqrt(pv[i]*1.0);
        r2s[i] = (float)(r*r);
        double disk = 3.14159265358979323846 * 1.0 * pv[i] / (double)nss[i];
        double el   = sqrt(2.0*disk/1.732);
        expf_[i] = (float)el;
        denf_[i] = (float)(el + 1e-8);
    }
    const float r2max = r2s[4];

    if (qi < NQ){
        const int b = qi / NPOINT;
        const float* __restrict__ P = pcd + b*NPTS*3;
        const float qx=g_newxyz[3*qi], qy=g_newxyz[3*qi+1], qz=g_newxyz[3*qi+2];

        // ---- phase 1: coalesced scan + warp-ballot compaction ----
        int cnt = 0;
        for (int base=0; base<NPTS; base+=32){
            const int j = base + lane;
            const float px=P[3*j], py=P[3*j+1], pz=P[3*j+2];
            const float dd = sqdist3(px,py,pz,qx,qy,qz);
            const bool hit = (dd <= r2max);
            const unsigned msk = __ballot_sync(0xffffffffu, hit);
            if (hit){
                const int pos = cnt + __popc(msk & ((1u<<lane)-1u));
                if (pos < UCAP) s_pts[w][pos] = make_float4(px,py,pz,dd);
            }
            cnt += __popc(msk);
        }
        if (cnt > UCAP) cnt = UCAP;
        __syncwarp();

        // ---- phase 2: per percentage ----
        #pragma unroll
        for (int i=0;i<5;i++){
            const int   ns  = nss[i];
            const float r2  = r2s[i];
            int K = 0;
            for (int base=0; base<cnt && K<ns; base+=32){
                const int m = base + lane;
                const bool sel = (m < cnt) && (s_pts[w][m].w <= r2);
                const unsigned msk = __ballot_sync(0xffffffffu, sel);
                if (sel){
                    const int pos = K + __popc(msk & ((1u<<lane)-1u));
                    if (pos < ns) s_sel[w][pos] = (unsigned char)m;
                }
                K += __popc(msk);
            }
            if (K > ns) K = ns;
            __syncwarp();

            const int Ppad = ns - K;
            float s = 0.f;
            const float4 p0 = s_pts[w][s_sel[w][0]];
            for (int r = lane; r < K; r += 32){
                const float4 a = s_pts[w][s_sel[w][r]];
                float m1 = 3.4e38f, m2 = 3.4e38f;
                for (int bb=0; bb<K; bb++){
                    const float4 pb = s_pts[w][s_sel[w][bb]];
                    const float dd = sqdist3(a.x,a.y,a.z,pb.x,pb.y,pb.z);
                    if (dd < m1){ m2 = m1; m1 = dd; }
                    else if (dd < m2){ m2 = dd; }
                }
                if (Ppad > 0){
                    const float dd = sqdist3(a.x,a.y,a.z,p0.x,p0.y,p0.z);
                    if (dd < m1){ m2 = m1; m1 = dd; } else if (dd < m2){ m2 = dd; }
                    if (Ppad > 1){
                        if (dd < m1){ m2 = m1; m1 = dd; } else if (dd < m2){ m2 = dd; }
                    }
                }
                const float rud = sqrtf(fabsf(__fadd_rn(m2, 1e-8f)));
                const float dv  = __fsub_rn(rud, expf_[i]);
                s = __fadd_rn(s, __fmul_rn(dv,dv)/denf_[i]);
            }
            if (lane == 0 && Ppad > 0){
                const float rud = sqrtf(fabsf(__fadd_rn(0.f, 1e-8f)));
                const float dv  = __fsub_rn(rud, expf_[i]);
                s = __fadd_rn(s, (float)Ppad * (__fmul_rn(dv,dv)/denf_[i]));
            }
            #pragma unroll
            for (int o=16;o;o>>=1) s += __shfl_down_sync(0xffffffffu, s, o);
            wsum[i] = s;
            __syncwarp();
        }
        if (lane == 0){
            #pragma unroll
            for (int i=0;i<5;i++) atomicAdd(&s_acc[i], wsum[i]);
        }
    }
    __syncthreads();
    if (tid < 5) atomicAdd(&g_uni_sum[tid], (double)s_acc[tid]);
    __syncthreads();

    // ---- finalization by the last block to finish ----
    if (tid == 0){
        __threadfence();
        const unsigned v = atomicAdd(&g_done, 1u);
        if (v == (unsigned)(UNIBLK - 1)){
            const double pvf[5]  = {0.004,0.008,0.01,0.012,0.016};
            const int    nssf[5] = {32,65,81,98,131};
            double u = 0.0;
            for (int i=0;i<5;i++){
                const double m = g_uni_sum[i] / ((double)NQ * (double)nssf[i]);
                const double wgt = (pvf[i]*100.0)*(pvf[i]*100.0);
                u += m*wgt;
            }
            u /= 5.0;
            out[0] = (float)u;
            out[1] = (float)(g_rep_sum / 131072.0);   // mean over B*N*4
        }
    }
}

extern "C" void kernel_launch(void* const* d_in, const int* in_sizes, int n_in,
                              void* d_out, int out_size){
    (void)in_sizes; (void)n_in; (void)out_size;
    const float* pcd = (const float*)d_in[0];
    float* out = (float*)d_out;

    init_kernel<<<1,32>>>();
    fps_rep_kernel<<<FPS_BLKS + NB*32, 256>>>(pcd);  // 16 FPS (4 clusters of 4) + 128 repulsion
    uni_fused_kernel<<<UNIBLK, 256>>>(pcd, out);     // 205 blocks; last one finalizes
}